// round 1
// baseline (speedup 1.0000x reference)
#include <cuda_runtime.h>
#include <cuda_bf16.h>

#define BATCH 8
#define FDIM 16
#define NPTS 2048
#define TILE 128

// Scratch for per-point squared norms and powered momenta (no cudaMalloc allowed)
__device__ float g_sqn[BATCH * NPTS];
__device__ float g_pm [BATCH * NPTS];

// ---------------------------------------------------------------------------
// Pre-kernel: sq_norms[b,n] = sum_f emb[b,f,n]^2 ; pm[b,n] = exp(2*alpha*log(m))
// ---------------------------------------------------------------------------
__global__ void qcd_pre_kernel(const float* __restrict__ emb,
                               const float* __restrict__ alpha_p)
{
    int idx = blockIdx.x * blockDim.x + threadIdx.x;  // b*NPTS + n
    if (idx >= BATCH * NPTS) return;
    int b = idx >> 11;          // / NPTS
    int n = idx & (NPTS - 1);   // % NPTS
    const float* base = emb + (size_t)b * FDIM * NPTS + n;
    float s = 0.0f;
#pragma unroll
    for (int f = 0; f < FDIM; ++f) {
        float v = base[f * NPTS];
        s = fmaf(v, v, s);
    }
    g_sqn[idx] = s;
    float m = base[4 * NPTS];
    float alpha = alpha_p[0];
    g_pm[idx] = expf(2.0f * alpha * logf(m));
}

// ---------------------------------------------------------------------------
// Fast exp on fma/alu pipes (avoids MUFU throughput wall).
// Valid for x in ~[-90, +1]; here x in [-35, +eps]. Rel err ~3e-6.
// ---------------------------------------------------------------------------
__device__ __forceinline__ float fast_expf(float x)
{
    const float LOG2E = 1.4426950408889634f;
    float t  = x * LOG2E;
    float kf = t + 12582912.0f;                       // 1.5*2^23 magic round
    int   k  = __float_as_int(kf) - 0x4B400000;       // round-to-nearest int
    float f  = t - (kf - 12582912.0f);                // f in [-0.5, 0.5]
    // degree-5 Taylor/minimax of 2^f
    float p = 0.0013333558f;
    p = fmaf(p, f, 0.0096181291f);
    p = fmaf(p, f, 0.0555041087f);
    p = fmaf(p, f, 0.2402265070f);
    p = fmaf(p, f, 0.6931471806f);
    p = fmaf(p, f, 1.0f);
    return __int_as_float(__float_as_int(p) + (k << 23));  // * 2^k
}

// ---------------------------------------------------------------------------
// Main kernel: one 128x128 (i,j) tile per block, 256 threads, 8x8 micro-tile.
// ---------------------------------------------------------------------------
__global__ __launch_bounds__(256, 2)
void qcd_main_kernel(const float* __restrict__ emb,
                     const float* __restrict__ beta_p,
                     float* __restrict__ out)
{
    __shared__ float As[FDIM][TILE];   // rows i
    __shared__ float Bs[FDIM][TILE];   // cols j
    __shared__ float sni[TILE], spi[TILE];
    __shared__ float snj[TILE], spj[TILE];

    const int jt = blockIdx.x;
    const int it = blockIdx.y;
    const int b  = blockIdx.z;
    const int i0 = it * TILE;
    const int j0 = jt * TILE;
    const int tid = threadIdx.x;

    const float* eb = emb + (size_t)b * FDIM * NPTS;

    // Load 16x128 A and B tiles (coalesced: 128 consecutive floats per f-row)
#pragma unroll
    for (int k = 0; k < 8; ++k) {
        int idx = tid + k * 256;
        int f = idx >> 7;
        int n = idx & 127;
        As[f][n] = eb[f * NPTS + i0 + n];
        Bs[f][n] = eb[f * NPTS + j0 + n];
    }
    if (tid < 128) {
        sni[tid] = g_sqn[b * NPTS + i0 + tid];
        spi[tid] = g_pm [b * NPTS + i0 + tid];
    } else {
        int t = tid - 128;
        snj[t] = g_sqn[b * NPTS + j0 + t];
        spj[t] = g_pm [b * NPTS + j0 + t];
    }
    __syncthreads();

    const int tx = tid & 15;   // j sub-tile: cols tx*8 .. tx*8+7
    const int ty = tid >> 4;   // i sub-tile: rows ty*8 .. ty*8+7

    float acc[8][8];
#pragma unroll
    for (int ii = 0; ii < 8; ++ii)
#pragma unroll
        for (int jj = 0; jj < 8; ++jj) acc[ii][jj] = 0.0f;

#pragma unroll
    for (int f = 0; f < FDIM; ++f) {
        float4 a0 = *(const float4*)&As[f][ty * 8];
        float4 a1 = *(const float4*)&As[f][ty * 8 + 4];
        float4 b0 = *(const float4*)&Bs[f][tx * 8];
        float4 b1 = *(const float4*)&Bs[f][tx * 8 + 4];
        float av[8] = {a0.x, a0.y, a0.z, a0.w, a1.x, a1.y, a1.z, a1.w};
        float bv[8] = {b0.x, b0.y, b0.z, b0.w, b1.x, b1.y, b1.z, b1.w};
#pragma unroll
        for (int ii = 0; ii < 8; ++ii)
#pragma unroll
            for (int jj = 0; jj < 8; ++jj)
                acc[ii][jj] = fmaf(av[ii], bv[jj], acc[ii][jj]);
    }

    // Epilogue
    const float beta = beta_p[0];
    const float nbsq = -beta * beta;

    float ni[8], pi[8], nj[8], pj[8];
#pragma unroll
    for (int k = 0; k < 8; ++k) {
        ni[k] = sni[ty * 8 + k];
        pi[k] = spi[ty * 8 + k];
        nj[k] = snj[tx * 8 + k];
        pj[k] = spj[tx * 8 + k];
    }

    float* orow = out + (size_t)b * NPTS * NPTS + (size_t)(i0 + ty * 8) * NPTS + j0 + tx * 8;

#pragma unroll
    for (int ii = 0; ii < 8; ++ii) {
        float w[8];
#pragma unroll
        for (int jj = 0; jj < 8; ++jj) {
            float sq = fmaf(-2.0f, acc[ii][jj], ni[ii] + nj[jj]);
            float mm = fminf(pi[ii], pj[jj]);
            float x  = nbsq * sq * mm;
            w[jj] = fast_expf(x);
        }
        float4* dst = (float4*)(orow + (size_t)ii * NPTS);
        dst[0] = make_float4(w[0], w[1], w[2], w[3]);
        dst[1] = make_float4(w[4], w[5], w[6], w[7]);
    }
}

// ---------------------------------------------------------------------------
extern "C" void kernel_launch(void* const* d_in, const int* in_sizes, int n_in,
                              void* d_out, int out_size)
{
    const float* emb     = (const float*)d_in[0];
    const float* alpha_p = (const float*)d_in[1];
    const float* beta_p  = (const float*)d_in[2];
    float* out = (float*)d_out;

    qcd_pre_kernel<<<(BATCH * NPTS + 255) / 256, 256>>>(emb, alpha_p);

    dim3 grid(NPTS / TILE, NPTS / TILE, BATCH);  // 16 x 16 x 8
    qcd_main_kernel<<<grid, 256>>>(emb, beta_p, out);
}

// round 2
// speedup vs baseline: 1.0006x; 1.0006x over previous
#include <cuda_runtime.h>
#include <cuda_bf16.h>

#define BATCH 8
#define FDIM 16
#define NPTS 2048
#define TILE 128

typedef unsigned long long u64;

// ---------------------------------------------------------------------------
// Packed f32x2 FMA (sm_100+ PTX only; ptxas won't auto-fuse from C++)
// ---------------------------------------------------------------------------
__device__ __forceinline__ float2 ffma2(float2 a, float2 b, float2 c)
{
    float2 d;
    asm("fma.rn.f32x2 %0, %1, %2, %3;"
        : "=l"(reinterpret_cast<u64&>(d))
        : "l"(reinterpret_cast<u64&>(a)),
          "l"(reinterpret_cast<u64&>(b)),
          "l"(reinterpret_cast<u64&>(c)));
    return d;
}

__device__ __forceinline__ float ex2f(float x)
{
    float y; asm("ex2.approx.ftz.f32 %0, %1;" : "=f"(y) : "f"(x)); return y;
}
__device__ __forceinline__ float lg2f(float x)
{
    float y; asm("lg2.approx.ftz.f32 %0, %1;" : "=f"(y) : "f"(x)); return y;
}

// ---------------------------------------------------------------------------
// One 128x128 (i,j) tile per block, 256 threads, 8x8 micro-tile.
// Norms + powered momenta computed in-block from the smem tiles (no pre-pass).
// ---------------------------------------------------------------------------
__global__ __launch_bounds__(256, 2)
void qcd_main_kernel(const float* __restrict__ emb,
                     const float* __restrict__ alpha_p,
                     const float* __restrict__ beta_p,
                     float* __restrict__ out)
{
    __shared__ float2 As2[FDIM][TILE];   // rows i, pre-broadcast (v,v) pairs
    __shared__ float  Bs [FDIM][TILE];   // cols j
    __shared__ float sni[TILE], spi[TILE];
    __shared__ float snj[TILE], spj[TILE];

    const int jt = blockIdx.x;
    const int it = blockIdx.y;
    const int b  = blockIdx.z;
    const int i0 = it * TILE;
    const int j0 = jt * TILE;
    const int tid = threadIdx.x;

    const float* eb = emb + (size_t)b * FDIM * NPTS;

    // Load 16x128 A (broadcast-packed) and B tiles; coalesced per f-row.
#pragma unroll
    for (int k = 0; k < 8; ++k) {
        int idx = tid + k * 256;
        int f = idx >> 7;
        int n = idx & 127;
        float a = eb[f * NPTS + i0 + n];
        As2[f][n] = make_float2(a, a);
        Bs[f][n]  = eb[f * NPTS + j0 + n];
    }
    __syncthreads();

    // Per-tile norms and m^(2*alpha), computed from smem (replaces pre-kernel)
    const float alpha2 = 2.0f * alpha_p[0];
    if (tid < 128) {
        float s = 0.0f;
#pragma unroll
        for (int f = 0; f < FDIM; ++f) {
            float v = As2[f][tid].x;
            s = fmaf(v, v, s);
        }
        sni[tid] = s;
        float m = As2[4][tid].x;
        spi[tid] = ex2f(alpha2 * lg2f(m));
    } else {
        int t = tid - 128;
        float s = 0.0f;
#pragma unroll
        for (int f = 0; f < FDIM; ++f) {
            float v = Bs[f][t];
            s = fmaf(v, v, s);
        }
        snj[t] = s;
        float m = Bs[4][t];
        spj[t] = ex2f(alpha2 * lg2f(m));
    }
    __syncthreads();

    const int tx = tid & 15;   // j sub-tile: cols tx*8 .. tx*8+7
    const int ty = tid >> 4;   // i sub-tile: rows ty*8 .. ty*8+7

    float2 acc[8][4];
#pragma unroll
    for (int ii = 0; ii < 8; ++ii)
#pragma unroll
        for (int jj = 0; jj < 4; ++jj) acc[ii][jj] = make_float2(0.0f, 0.0f);

    // Gram mainloop: packed f32x2 FMAs. A operand is a broadcast pair straight
    // from smem (LDS.64, conflict-free broadcast); B pairs come from LDS.128.
#pragma unroll
    for (int f = 0; f < FDIM; ++f) {
        float2 av[8];
#pragma unroll
        for (int ii = 0; ii < 8; ++ii) av[ii] = As2[f][ty * 8 + ii];

        float4 q0 = *(const float4*)&Bs[f][tx * 8];
        float4 q1 = *(const float4*)&Bs[f][tx * 8 + 4];
        float2 bv[4] = { make_float2(q0.x, q0.y), make_float2(q0.z, q0.w),
                         make_float2(q1.x, q1.y), make_float2(q1.z, q1.w) };
#pragma unroll
        for (int ii = 0; ii < 8; ++ii)
#pragma unroll
            for (int jj = 0; jj < 4; ++jj)
                acc[ii][jj] = ffma2(av[ii], bv[jj], acc[ii][jj]);
    }

    // Epilogue: w = ex2( mm * ( (c*ni + c*nj) + (-2c)*gram ) ),  c = -beta^2*log2(e)
    const float beta = beta_p[0];
    const float cl   = -(beta * beta) * 1.4426950408889634f;
    const float m2cl = -2.0f * cl;

    float cni[8], pi[8], cnj[8], pj[8];
#pragma unroll
    for (int k = 0; k < 8; ++k) {
        cni[k] = cl * sni[ty * 8 + k];
        pi[k]  = spi[ty * 8 + k];
        cnj[k] = cl * snj[tx * 8 + k];
        pj[k]  = spj[tx * 8 + k];
    }

    float* orow = out + (size_t)b * NPTS * NPTS + (size_t)(i0 + ty * 8) * NPTS + j0 + tx * 8;

#pragma unroll
    for (int ii = 0; ii < 8; ++ii) {
        float w[8];
#pragma unroll
        for (int jj = 0; jj < 4; ++jj) {
            float2 g = acc[ii][jj];
            int je = jj * 2;
            float x0 = fmaf(m2cl, g.x, cni[ii] + cnj[je]);
            float x1 = fmaf(m2cl, g.y, cni[ii] + cnj[je + 1]);
            float mm0 = fminf(pi[ii], pj[je]);
            float mm1 = fminf(pi[ii], pj[je + 1]);
            w[je]     = ex2f(mm0 * x0);
            w[je + 1] = ex2f(mm1 * x1);
        }
        float4* dst = (float4*)(orow + (size_t)ii * NPTS);
        dst[0] = make_float4(w[0], w[1], w[2], w[3]);
        dst[1] = make_float4(w[4], w[5], w[6], w[7]);
    }
}

// ---------------------------------------------------------------------------
extern "C" void kernel_launch(void* const* d_in, const int* in_sizes, int n_in,
                              void* d_out, int out_size)
{
    const float* emb     = (const float*)d_in[0];
    const float* alpha_p = (const float*)d_in[1];
    const float* beta_p  = (const float*)d_in[2];
    float* out = (float*)d_out;

    dim3 grid(NPTS / TILE, NPTS / TILE, BATCH);  // 16 x 16 x 8
    qcd_main_kernel<<<grid, 256>>>(emb, alpha_p, beta_p, out);
}

// round 3
// speedup vs baseline: 1.2179x; 1.2172x over previous
#include <cuda_runtime.h>
#include <cuda_bf16.h>

#define BATCH 8
#define FDIM 16
#define NPTS 2048
#define TILE 128
#define NTILE (NPTS / TILE)            // 16
#define NTRI  (NTILE * (NTILE + 1) / 2) // 136

typedef unsigned long long u64;

__device__ __forceinline__ float2 ffma2(float2 a, float2 b, float2 c)
{
    float2 d;
    asm("fma.rn.f32x2 %0, %1, %2, %3;"
        : "=l"(reinterpret_cast<u64&>(d))
        : "l"(reinterpret_cast<u64&>(a)),
          "l"(reinterpret_cast<u64&>(b)),
          "l"(reinterpret_cast<u64&>(c)));
    return d;
}
__device__ __forceinline__ float ex2f(float x)
{ float y; asm("ex2.approx.ftz.f32 %0, %1;" : "=f"(y) : "f"(x)); return y; }
__device__ __forceinline__ float lg2f(float x)
{ float y; asm("lg2.approx.ftz.f32 %0, %1;" : "=f"(y) : "f"(x)); return y; }

// 16B-unit index into the 64x128-float staging buffer, XOR-swizzled so both the
// transposed STS and the row-wise LDS land nearly conflict-free.
__device__ __forceinline__ int tsw(int rl, int c4)
{
    return rl * 32 + (c4 ^ ((rl >> 2) & 31));
}

// ---------------------------------------------------------------------------
// One 128x128 (i,j) tile per block, upper-triangular tiles only (it <= jt).
// Off-diagonal tiles also emit the transposed block via smem staging.
// ---------------------------------------------------------------------------
__global__ __launch_bounds__(256, 2)
void qcd_main_kernel(const float* __restrict__ emb,
                     const float* __restrict__ alpha_p,
                     const float* __restrict__ beta_p,
                     float* __restrict__ out)
{
    // 32KB region: tiles (As2 16KB + Bs 8KB) alive through mainloop,
    // then reused as the 64x128 transpose staging buffer T.
    __shared__ __align__(16) unsigned char smraw[32 * 1024];
    __shared__ float sni[TILE], spi[TILE], snj[TILE], spj[TILE];

    float2 (*As2)[TILE] = reinterpret_cast<float2(*)[TILE]>(smraw);
    float  (*Bs )[TILE] = reinterpret_cast<float (*)[TILE]>(smraw + sizeof(float2) * FDIM * TILE);
    float4* Tq          = reinterpret_cast<float4*>(smraw);

    // Triangular tile index: t -> (it, jt), it <= jt
    const int t = blockIdx.x;
    int jt = (int)((sqrtf(8.0f * (float)t + 1.0f) - 1.0f) * 0.5f);
    if ((jt + 1) * (jt + 2) / 2 <= t) jt++;
    else if (jt * (jt + 1) / 2 > t)   jt--;
    const int it = t - jt * (jt + 1) / 2;

    const int b  = blockIdx.y;
    const int i0 = it * TILE;
    const int j0 = jt * TILE;
    const int tid = threadIdx.x;

    const float* eb = emb + (size_t)b * FDIM * NPTS;

    // Vectorized tile loads: 1024 float4 total, 4 per thread.
#pragma unroll
    for (int k = 0; k < 4; ++k) {
        int q = tid + k * 256;          // 0..1023
        if (q < 512) {                  // A tile: 16 rows x 32 float4
            int f  = q >> 5;
            int n4 = q & 31;
            float4 v = *(const float4*)&eb[f * NPTS + i0 + n4 * 4];
            float4* d = (float4*)&As2[f][n4 * 4];
            d[0] = make_float4(v.x, v.x, v.y, v.y);
            d[1] = make_float4(v.z, v.z, v.w, v.w);
        } else {                        // B tile
            int q2 = q - 512;
            int f  = q2 >> 5;
            int n4 = q2 & 31;
            float4 v = *(const float4*)&eb[f * NPTS + j0 + n4 * 4];
            *(float4*)&Bs[f][n4 * 4] = v;
        }
    }
    __syncthreads();

    // Per-tile norms and m^(2*alpha)
    const float alpha2 = 2.0f * alpha_p[0];
    if (tid < 128) {
        float s = 0.0f;
#pragma unroll
        for (int f = 0; f < FDIM; ++f) { float v = As2[f][tid].x; s = fmaf(v, v, s); }
        sni[tid] = s;
        spi[tid] = ex2f(alpha2 * lg2f(As2[4][tid].x));
    } else {
        int tt = tid - 128;
        float s = 0.0f;
#pragma unroll
        for (int f = 0; f < FDIM; ++f) { float v = Bs[f][tt]; s = fmaf(v, v, s); }
        snj[tt] = s;
        spj[tt] = ex2f(alpha2 * lg2f(Bs[4][tt]));
    }
    __syncthreads();

    const int tx = tid & 15;   // j sub-tile
    const int ty = tid >> 4;   // i sub-tile

    float2 acc[8][4];
#pragma unroll
    for (int ii = 0; ii < 8; ++ii)
#pragma unroll
        for (int jj = 0; jj < 4; ++jj) acc[ii][jj] = make_float2(0.0f, 0.0f);

#pragma unroll
    for (int f = 0; f < FDIM; ++f) {
        float2 av[8];
#pragma unroll
        for (int ii = 0; ii < 8; ++ii) av[ii] = As2[f][ty * 8 + ii];
        float4 q0 = *(const float4*)&Bs[f][tx * 8];
        float4 q1 = *(const float4*)&Bs[f][tx * 8 + 4];
        float2 bv[4] = { make_float2(q0.x, q0.y), make_float2(q0.z, q0.w),
                         make_float2(q1.x, q1.y), make_float2(q1.z, q1.w) };
#pragma unroll
        for (int ii = 0; ii < 8; ++ii)
#pragma unroll
            for (int jj = 0; jj < 4; ++jj)
                acc[ii][jj] = ffma2(av[ii], bv[jj], acc[ii][jj]);
    }

    // Epilogue constants: w = ex2( mm * fma(-2c, gram, c*ni + c*nj) ), c = -beta^2*log2e
    const float beta = beta_p[0];
    const float cl   = -(beta * beta) * 1.4426950408889634f;
    const float m2cl = -2.0f * cl;

    float cni[8], pi[8], cnj[8], pj[8];
#pragma unroll
    for (int k = 0; k < 8; ++k) {
        cni[k] = cl * sni[ty * 8 + k];
        pi[k]  = spi[ty * 8 + k];
        cnj[k] = cl * snj[tx * 8 + k];
        pj[k]  = spj[tx * 8 + k];
    }

    // Direct (i,j) block store
    float* orow = out + (size_t)b * NPTS * NPTS + (size_t)(i0 + ty * 8) * NPTS + j0 + tx * 8;
#pragma unroll
    for (int ii = 0; ii < 8; ++ii) {
        float w[8];
#pragma unroll
        for (int jj = 0; jj < 4; ++jj) {
            float2 g = acc[ii][jj];
            int je = jj * 2;
            float x0 = fmaf(m2cl, g.x, cni[ii] + cnj[je]);
            float x1 = fmaf(m2cl, g.y, cni[ii] + cnj[je + 1]);
            w[je]     = ex2f(fminf(pi[ii], pj[je])     * x0);
            w[je + 1] = ex2f(fminf(pi[ii], pj[je + 1]) * x1);
        }
        float4* dst = (float4*)(orow + (size_t)ii * NPTS);
        dst[0] = make_float4(w[0], w[1], w[2], w[3]);
        dst[1] = make_float4(w[4], w[5], w[6], w[7]);
    }

    // Mirror (j,i) block for off-diagonal tiles, staged 64 rows at a time.
    if (it != jt) {
#pragma unroll
        for (int h = 0; h < 2; ++h) {
            __syncthreads();   // staging buffer region free / previous pass consumed
            if ((tx >> 3) == h) {
                // Transposed store: T[rl = local j][c = local i], recompute w per column.
#pragma unroll
                for (int jj = 0; jj < 8; ++jj) {
                    int rl = (tx & 7) * 8 + jj;
                    float wc[8];
#pragma unroll
                    for (int ii = 0; ii < 8; ++ii) {
                        float g = (jj & 1) ? acc[ii][jj >> 1].y : acc[ii][jj >> 1].x;
                        float x = fmaf(m2cl, g, cni[ii] + cnj[jj]);
                        wc[ii]  = ex2f(fminf(pi[ii], pj[jj]) * x);
                    }
                    Tq[tsw(rl, 2 * ty + 0)] = make_float4(wc[0], wc[1], wc[2], wc[3]);
                    Tq[tsw(rl, 2 * ty + 1)] = make_float4(wc[4], wc[5], wc[6], wc[7]);
                }
            }
            __syncthreads();
            // Coalesced readback + store: 64 rows x 128 cols, all 256 threads.
#pragma unroll
            for (int m = 0; m < 2; ++m) {
                int rl  = m * 32 + (tid >> 3);
                float* mrow = out + (size_t)b * NPTS * NPTS
                                  + (size_t)(j0 + h * 64 + rl) * NPTS + i0;
#pragma unroll
                for (int k = 0; k < 4; ++k) {
                    int c4 = (tid & 7) + k * 8;
                    *(float4*)(mrow + c4 * 4) = Tq[tsw(rl, c4)];
                }
            }
        }
    }
}

// ---------------------------------------------------------------------------
extern "C" void kernel_launch(void* const* d_in, const int* in_sizes, int n_in,
                              void* d_out, int out_size)
{
    const float* emb     = (const float*)d_in[0];
    const float* alpha_p = (const float*)d_in[1];
    const float* beta_p  = (const float*)d_in[2];
    float* out = (float*)d_out;

    dim3 grid(NTRI, BATCH);   // 136 x 8 = 1088 CTAs
    qcd_main_kernel<<<grid, 256>>>(emb, alpha_p, beta_p, out);
}